// round 9
// baseline (speedup 1.0000x reference)
#include <cuda_runtime.h>
#include <cuda_bf16.h>
#include <stdint.h>

#define N_NODES_C 100000
#define N_EDGES_C 1600000
#define IN_DIM 32
#define HID_DIM 64
#define OUT_DIM 8
#define MAX_DEG 64
#define NPB 128              // nodes per k_gemm block (MMA M)

typedef unsigned long long ull;

// ---------------- scratch (device globals; no allocation allowed) ----------
__device__ int   g_cnt[N_NODES_C];
__device__ int   g_csr[N_NODES_C * MAX_DEG];
__device__ float g_p  [N_NODES_C * OUT_DIM];
__device__ float g_r  [N_NODES_C * OUT_DIM];
__device__ int   g_ei_is32;

// ---------------- warp-MMA helpers (sm_80+ PTX, legal on compute_103) --------
__device__ __forceinline__ uint32_t smem_u32(const void* p) {
    uint32_t a;
    asm("{ .reg .u64 t; cvta.to.shared.u64 t, %1; cvt.u32.u64 %0, t; }"
        : "=r"(a) : "l"(p));
    return a;
}
__device__ __forceinline__ void ldsm_x4(uint32_t addr, uint32_t& r0, uint32_t& r1,
                                        uint32_t& r2, uint32_t& r3) {
    asm volatile("ldmatrix.sync.aligned.m8n8.x4.shared.b16 {%0,%1,%2,%3}, [%4];"
                 : "=r"(r0), "=r"(r1), "=r"(r2), "=r"(r3) : "r"(addr) : "memory");
}
__device__ __forceinline__ void mma_bf16(float* c, const uint32_t* a,
                                         uint32_t b0, uint32_t b1) {
    asm volatile("mma.sync.aligned.m16n8k16.row.col.f32.bf16.bf16.f32 "
                 "{%0,%1,%2,%3}, {%4,%5,%6,%7}, {%8,%9}, {%0,%1,%2,%3};"
                 : "+f"(c[0]), "+f"(c[1]), "+f"(c[2]), "+f"(c[3])
                 : "r"(a[0]), "r"(a[1]), "r"(a[2]), "r"(a[3]), "r"(b0), "r"(b1));
}
__device__ __forceinline__ void f2bf_hilo(float v, unsigned short& h, unsigned short& l) {
    __nv_bfloat16 hb = __float2bfloat16_rn(v);
    float r = v - __bfloat162float(hb);
    __nv_bfloat16 lb = __float2bfloat16_rn(r);
    h = __bfloat16_as_ushort(hb);
    l = __bfloat16_as_ushort(lb);
}
// convert float4 -> (hi uint2, lo uint2)
__device__ __forceinline__ void f4_to_hilo(float4 v, uint2& hu, uint2& lu) {
    float vv[4] = {v.x, v.y, v.z, v.w};
    unsigned short hs[4], ls[4];
#pragma unroll
    for (int k = 0; k < 4; ++k) f2bf_hilo(vv[k], hs[k], ls[k]);
    hu.x = (uint32_t)hs[0] | ((uint32_t)hs[1] << 16);
    hu.y = (uint32_t)hs[2] | ((uint32_t)hs[3] << 16);
    lu.x = (uint32_t)ls[0] | ((uint32_t)ls[1] << 16);
    lu.y = (uint32_t)ls[2] | ((uint32_t)ls[3] << 16);
}

// smem layout for k_gemm (dynamic): strides in bf16 elements
#define STRA 136                         // 128 data + 8 pad (272B rows)
#define OFF_A  0                         // A/H: 128 rows -> 34816 B
#define OFF_B  34816                     // B (Wcat): 64 rows -> 17408 B
#define OFF_B2 52224                     // B2 (W2cat): 16 rows -> 4352 B
#define OFF_B1 56576                     // b1: 64 floats = 256 B
#define SMEM_GEMM 56832

// ---------------- kernel 1: zero counters + detect edge dtype ---------------
__global__ void k_zero(const void* __restrict__ ei) {
    const int stride = gridDim.x * blockDim.x;
    int t = blockIdx.x * blockDim.x + threadIdx.x;
    if (t == 0) {
        const long long* p = (const long long*)ei;
        int is32 = 0;
        for (int i = 0; i < 128; ++i) {
            long long v = p[i];
            if (v < 0 || v >= (long long)N_NODES_C) { is32 = 1; break; }
        }
        g_ei_is32 = is32;
    }
    for (int i = t; i < N_NODES_C; i += stride) g_cnt[i] = 0;
}

// ---------------- kernel 2: build padded CSR --------------------------------
__global__ void __launch_bounds__(256) k_fill(const void* __restrict__ ei) {
    int e = blockIdx.x * blockDim.x + threadIdx.x;
    if (e >= N_EDGES_C) return;
    int src, dst;
    if (g_ei_is32) {
        const int* p = (const int*)ei;
        src = p[e];
        dst = p[N_EDGES_C + e];
    } else {
        const long long* p = (const long long*)ei;
        src = (int)p[e];
        dst = (int)p[N_EDGES_C + e];
    }
    int slot = atomicAdd(&g_cnt[dst], 1);
    if (slot < MAX_DEG) g_csr[dst * MAX_DEG + slot] = src;
}

// ---------------- kernel 3: fused gather + double-MMA layer -----------------
// Stage weights; gather-mean x[src] per node (2 threads/node) straight into
// the bf16 hi/lo A-tile; MMA1 -> relu -> MMA2 -> p/r.
__global__ void __launch_bounds__(256, 2) k_gemm(const float* __restrict__ x,
                                                 const float* __restrict__ W1l,
                                                 const float* __restrict__ b1,
                                                 const float* __restrict__ W1r,
                                                 const float* __restrict__ W2l,
                                                 const float* __restrict__ W2r) {
    extern __shared__ unsigned char dynsmem[];
    unsigned short* sA  = reinterpret_cast<unsigned short*>(dynsmem + OFF_A);
    unsigned short* sB  = reinterpret_cast<unsigned short*>(dynsmem + OFF_B);
    unsigned short* sB2 = reinterpret_cast<unsigned short*>(dynsmem + OFF_B2);
    float* sb1 = reinterpret_cast<float*>(dynsmem + OFF_B1);

    const uint32_t sA_u  = smem_u32(sA);
    const uint32_t sB_u  = smem_u32(sB);
    const uint32_t sB2_u = smem_u32(sB2);

    int t = threadIdx.x;
    int wid = t >> 5, lane = t & 31;
    int base = blockIdx.x * NPB;

    // ---- stage B rows (Wcat [o][f]): [hi(64) | lo(64)] ----
    for (int idx = t; idx < 64 * 16; idx += 256) {
        int o = idx >> 4, f4 = idx & 15;
        float4 v = (f4 < 8)
            ? *reinterpret_cast<const float4*>(W1l + o * IN_DIM + f4 * 4)
            : *reinterpret_cast<const float4*>(W1r + o * IN_DIM + (f4 - 8) * 4);
        uint2 hu, lu;
        f4_to_hilo(v, hu, lu);
        *reinterpret_cast<uint2*>(sB + o * STRA + f4 * 4)      = hu;
        *reinterpret_cast<uint2*>(sB + o * STRA + 64 + f4 * 4) = lu;
    }
    // ---- stage B2 rows (W2cat [16][64]: rows 0-7 = W2l, 8-15 = W2r) ----
    for (int idx = t; idx < 16 * 16; idx += 256) {
        int o2 = idx >> 4, f4 = idx & 15;
        const float* srcw = (o2 < 8) ? (W2l + o2 * HID_DIM) : (W2r + (o2 - 8) * HID_DIM);
        float4 v = *reinterpret_cast<const float4*>(srcw + f4 * 4);
        uint2 hu, lu;
        f4_to_hilo(v, hu, lu);
        *reinterpret_cast<uint2*>(sB2 + o2 * STRA + f4 * 4)      = hu;
        *reinterpret_cast<uint2*>(sB2 + o2 * STRA + 64 + f4 * 4) = lu;
    }
    if (t < HID_DIM) sb1[t] = b1[t];

    // ---- fused gather + A staging: 2 threads per node, 16 feats each ----
    {
        int n = t >> 1, q = t & 1;       // node-local, feature half
        int node = base + n;
        int fb = q * 16;                 // feature base (0 or 16)

        float4 xs0 = make_float4(0.f, 0.f, 0.f, 0.f), xs1 = xs0, xs2 = xs0, xs3 = xs0;
        float4 a0 = xs0, a1 = xs0, a2 = xs0, a3 = xs0;
        float inv = 1.0f;

        if (node < N_NODES_C) {
            const float* xrow = x + (size_t)node * IN_DIM + fb;
            xs0 = *reinterpret_cast<const float4*>(xrow);
            xs1 = *reinterpret_cast<const float4*>(xrow + 4);
            xs2 = *reinterpret_cast<const float4*>(xrow + 8);
            xs3 = *reinterpret_cast<const float4*>(xrow + 12);

            int deg = min(g_cnt[node], MAX_DEG);
            const int* row = g_csr + node * MAX_DEG;
            int j = 0;
            for (; j + 2 <= deg; j += 2) {
                const float* pa = x + (size_t)row[j]     * IN_DIM + fb;
                const float* pb = x + (size_t)row[j + 1] * IN_DIM + fb;
                float4 va0 = *reinterpret_cast<const float4*>(pa);
                float4 va1 = *reinterpret_cast<const float4*>(pa + 4);
                float4 va2 = *reinterpret_cast<const float4*>(pa + 8);
                float4 va3 = *reinterpret_cast<const float4*>(pa + 12);
                float4 vb0 = *reinterpret_cast<const float4*>(pb);
                float4 vb1 = *reinterpret_cast<const float4*>(pb + 4);
                float4 vb2 = *reinterpret_cast<const float4*>(pb + 8);
                float4 vb3 = *reinterpret_cast<const float4*>(pb + 12);
                a0.x += va0.x + vb0.x; a0.y += va0.y + vb0.y;
                a0.z += va0.z + vb0.z; a0.w += va0.w + vb0.w;
                a1.x += va1.x + vb1.x; a1.y += va1.y + vb1.y;
                a1.z += va1.z + vb1.z; a1.w += va1.w + vb1.w;
                a2.x += va2.x + vb2.x; a2.y += va2.y + vb2.y;
                a2.z += va2.z + vb2.z; a2.w += va2.w + vb2.w;
                a3.x += va3.x + vb3.x; a3.y += va3.y + vb3.y;
                a3.z += va3.z + vb3.z; a3.w += va3.w + vb3.w;
            }
            if (j < deg) {
                const float* pa = x + (size_t)row[j] * IN_DIM + fb;
                float4 va0 = *reinterpret_cast<const float4*>(pa);
                float4 va1 = *reinterpret_cast<const float4*>(pa + 4);
                float4 va2 = *reinterpret_cast<const float4*>(pa + 8);
                float4 va3 = *reinterpret_cast<const float4*>(pa + 12);
                a0.x += va0.x; a0.y += va0.y; a0.z += va0.z; a0.w += va0.w;
                a1.x += va1.x; a1.y += va1.y; a1.z += va1.z; a1.w += va1.w;
                a2.x += va2.x; a2.y += va2.y; a2.z += va2.z; a2.w += va2.w;
                a3.x += va3.x; a3.y += va3.y; a3.z += va3.z; a3.w += va3.w;
            }
            inv = 1.0f / fmaxf((float)deg, 1.0f);
        }

        float4 agg[4] = {a0, a1, a2, a3};
        float4 xsv[4] = {xs0, xs1, xs2, xs3};
#pragma unroll
        for (int k = 0; k < 4; ++k) {
            float4 m = make_float4(agg[k].x * inv, agg[k].y * inv,
                                   agg[k].z * inv, agg[k].w * inv);
            uint2 hu, lu;
            f4_to_hilo(m, hu, lu);
            // agg: hi cols [0,32), lo cols [64,96)
            *reinterpret_cast<uint2*>(sA + n * STRA + fb + k * 4)      = hu;
            *reinterpret_cast<uint2*>(sA + n * STRA + 64 + fb + k * 4) = lu;
            f4_to_hilo(xsv[k], hu, lu);
            // x: hi cols [32,64), lo cols [96,128)
            *reinterpret_cast<uint2*>(sA + n * STRA + 32 + fb + k * 4) = hu;
            *reinterpret_cast<uint2*>(sA + n * STRA + 96 + fb + k * 4) = lu;
        }
    }
    __syncthreads();   // the only block-wide sync

    // fragment base addresses (identical addressing for MMA1 and MMA2 A)
    const uint32_t a_base = sA_u + (uint32_t)(((wid * 16 + (lane & 15)) * STRA + (lane >> 4) * 8) * 2);
    const int q = lane >> 3, rr = lane & 7;
    const uint32_t b_base  = sB_u  + (uint32_t)((((q >> 1) * 8 + rr) * STRA + (q & 1) * 8) * 2);
    const uint32_t b2_base = sB2_u + (uint32_t)((((q >> 1) * 8 + rr) * STRA + (q & 1) * 8) * 2);

    const int ka_tab[12] = {0, 1, 2, 3, 4, 5, 6, 7, 0, 1, 2, 3};   // A: hi,lo,hi
    const int kb_tab[12] = {0, 1, 2, 3, 0, 1, 2, 3, 4, 5, 6, 7};   // B: hi,hi,lo

    // ---- MMA1: C[8 ntiles][4] ----
    float c[8][4];
#pragma unroll
    for (int nt = 0; nt < 8; ++nt)
#pragma unroll
        for (int k = 0; k < 4; ++k) c[nt][k] = 0.f;
#pragma unroll
    for (int s = 0; s < 12; ++s) {
        uint32_t a[4];
        ldsm_x4(a_base + (uint32_t)(ka_tab[s] * 32), a[0], a[1], a[2], a[3]);
        uint32_t koff = (uint32_t)(kb_tab[s] * 32);
#pragma unroll
        for (int np = 0; np < 4; ++np) {
            uint32_t b0, b1v, b2v, b3;
            ldsm_x4(b_base + (uint32_t)(np * 16 * STRA * 2) + koff, b0, b1v, b2v, b3);
            mma_bf16(c[2 * np],     a, b0, b1v);
            mma_bf16(c[2 * np + 1], a, b2v, b3);
        }
    }

    // ---- warp-private epilogue: relu(h)+b1 -> own A-slab (bf16 hi/lo) ----
    __syncwarp();
    {
        int g = lane >> 2, cc = lane & 3;
        int m0 = wid * 16 + g;
#pragma unroll
        for (int nt = 0; nt < 8; ++nt) {
            int o0 = nt * 8 + 2 * cc;
            float bi0 = sb1[o0], bi1 = sb1[o0 + 1];
            float v0 = fmaxf(c[nt][0] + bi0, 0.f);
            float v1 = fmaxf(c[nt][1] + bi1, 0.f);
            float v2 = fmaxf(c[nt][2] + bi0, 0.f);
            float v3 = fmaxf(c[nt][3] + bi1, 0.f);
            unsigned short h0, l0, h1, l1, h2, l2, h3, l3;
            f2bf_hilo(v0, h0, l0); f2bf_hilo(v1, h1, l1);
            f2bf_hilo(v2, h2, l2); f2bf_hilo(v3, h3, l3);
            *reinterpret_cast<uint32_t*>(sA + m0 * STRA + o0)            = (uint32_t)h0 | ((uint32_t)h1 << 16);
            *reinterpret_cast<uint32_t*>(sA + m0 * STRA + 64 + o0)       = (uint32_t)l0 | ((uint32_t)l1 << 16);
            *reinterpret_cast<uint32_t*>(sA + (m0 + 8) * STRA + o0)      = (uint32_t)h2 | ((uint32_t)h3 << 16);
            *reinterpret_cast<uint32_t*>(sA + (m0 + 8) * STRA + 64 + o0) = (uint32_t)l2 | ((uint32_t)l3 << 16);
        }
    }
    __syncwarp();

    // ---- MMA2: [p|r][128x16] = H @ W2cat^T ----
    float c2[2][4];
#pragma unroll
    for (int nt = 0; nt < 2; ++nt)
#pragma unroll
        for (int k = 0; k < 4; ++k) c2[nt][k] = 0.f;
#pragma unroll
    for (int s = 0; s < 12; ++s) {
        uint32_t a[4];
        ldsm_x4(a_base + (uint32_t)(ka_tab[s] * 32), a[0], a[1], a[2], a[3]);
        uint32_t b0, b1v, b2v, b3;
        ldsm_x4(b2_base + (uint32_t)(kb_tab[s] * 32), b0, b1v, b2v, b3);
        mma_bf16(c2[0], a, b0, b1v);   // cols 0-7  = p
        mma_bf16(c2[1], a, b2v, b3);   // cols 8-15 = r
    }

    // ---- store p/r from fragments ----
    {
        int g = lane >> 2, cc = lane & 3;
        int m0 = wid * 16 + g;
        int n0 = base + m0, n1 = base + m0 + 8;
        if (n0 < N_NODES_C) {
            *reinterpret_cast<float2*>(g_p + (size_t)n0 * OUT_DIM + 2 * cc) =
                make_float2(c2[0][0], c2[0][1]);
            *reinterpret_cast<float2*>(g_r + (size_t)n0 * OUT_DIM + 2 * cc) =
                make_float2(c2[1][0], c2[1][1]);
        }
        if (n1 < N_NODES_C) {
            *reinterpret_cast<float2*>(g_p + (size_t)n1 * OUT_DIM + 2 * cc) =
                make_float2(c2[0][2], c2[0][3]);
            *reinterpret_cast<float2*>(g_r + (size_t)n1 * OUT_DIM + 2 * cc) =
                make_float2(c2[1][2], c2[1][3]);
        }
    }
}

// ---------------- kernel 4: layer-2 gather-mean + finalize (float4) ---------
__global__ void __launch_bounds__(256) k_layerB(const float* __restrict__ b2,
                                                float* __restrict__ out) {
    int tid = threadIdx.x, warp = tid >> 5, lane = tid & 31;
    int jl = lane >> 1, q = lane & 1;
    float4 b4 = *reinterpret_cast<const float4*>(b2 + q * 4);

    int node = blockIdx.x * 8 + warp;
    if (node >= N_NODES_C) return;

    int deg = min(g_cnt[node], MAX_DEG);
    const int* row = g_csr + node * MAX_DEG;
    int s0 = (lane      < deg) ? row[lane]      : 0;
    int s1 = (lane + 32 < deg) ? row[lane + 32] : 0;

    float4 acc = make_float4(0.f, 0.f, 0.f, 0.f);
    int rounds = (deg + 15) >> 4;
    for (int tr = 0; tr < rounds; ++tr) {
        int j = tr * 16 + jl;
        int s = (tr < 2) ? s0 : s1;
        int src = __shfl_sync(0xffffffffu, s, j & 31);
        if (j < deg) {
            float4 v = *reinterpret_cast<const float4*>(g_p + (size_t)src * OUT_DIM + q * 4);
            acc.x += v.x; acc.y += v.y; acc.z += v.z; acc.w += v.w;
        }
    }
#pragma unroll
    for (int off = 2; off <= 16; off <<= 1) {
        acc.x += __shfl_xor_sync(0xffffffffu, acc.x, off);
        acc.y += __shfl_xor_sync(0xffffffffu, acc.y, off);
        acc.z += __shfl_xor_sync(0xffffffffu, acc.z, off);
        acc.w += __shfl_xor_sync(0xffffffffu, acc.w, off);
    }
    if (lane < 2) {
        float inv = 1.0f / fmaxf((float)deg, 1.0f);
        float4 r = *reinterpret_cast<const float4*>(g_r + (size_t)node * OUT_DIM + q * 4);
        float4 o4;
        o4.x = fmaf(acc.x, inv, b4.x) + r.x;
        o4.y = fmaf(acc.y, inv, b4.y) + r.y;
        o4.z = fmaf(acc.z, inv, b4.z) + r.z;
        o4.w = fmaf(acc.w, inv, b4.w) + r.w;
        *reinterpret_cast<float4*>(out + (size_t)node * OUT_DIM + q * 4) = o4;
    }
}

// ---------------- launcher ---------------------------------------------------
extern "C" void kernel_launch(void* const* d_in, const int* in_sizes, int n_in,
                              void* d_out, int out_size) {
    int ix, iei, iW1l, ib1, iW1r, iW2l, ib2, iW2r;
    if (in_sizes[0] > 1000000) {        // dict order (x first)
        ix = 0; iei = 1; iW1l = 2; ib1 = 3; iW1r = 4; iW2l = 5; ib2 = 6; iW2r = 7;
    } else {                            // alphabetical
        iW1l = 0; iW1r = 1; iW2l = 2; iW2r = 3; ib1 = 4; ib2 = 5; iei = 6; ix = 7;
    }
    const float* x   = (const float*)d_in[ix];
    const void*  ei  = d_in[iei];
    const float* W1l = (const float*)d_in[iW1l];
    const float* b1  = (const float*)d_in[ib1];
    const float* W1r = (const float*)d_in[iW1r];
    const float* W2l = (const float*)d_in[iW2l];
    const float* b2  = (const float*)d_in[ib2];
    const float* W2r = (const float*)d_in[iW2r];
    float* out = (float*)d_out;

    static int smem_set = 0;
    if (!smem_set) {
        cudaFuncSetAttribute(k_gemm, cudaFuncAttributeMaxDynamicSharedMemorySize, SMEM_GEMM);
        cudaFuncSetAttribute(k_gemm, cudaFuncAttributePreferredSharedMemoryCarveout, 100);
        smem_set = 1;
    }

    k_zero<<<512, 256>>>(ei);
    k_fill<<<(N_EDGES_C + 255) / 256, 256>>>(ei);
    k_gemm<<<(N_NODES_C + NPB - 1) / NPB, 256, SMEM_GEMM>>>(x, W1l, b1, W1r, W2l, W2r);
    k_layerB<<<(N_NODES_C + 7) / 8, 256>>>(b2, out);
}

// round 10
// speedup vs baseline: 1.1361x; 1.1361x over previous
#include <cuda_runtime.h>
#include <cuda_bf16.h>
#include <stdint.h>

#define N_NODES_C 100000
#define N_EDGES_C 1600000
#define IN_DIM 32
#define HID_DIM 64
#define OUT_DIM 8
#define MAX_DEG 64
#define NPB 128              // nodes per k_gemm block (MMA M)

typedef unsigned long long ull;

// ---------------- scratch (device globals; no allocation allowed) ----------
__device__ int   g_cnt[N_NODES_C];
__device__ int   g_csr[N_NODES_C * MAX_DEG];
__device__ float g_agg[N_NODES_C * IN_DIM];
__device__ float g_p  [N_NODES_C * OUT_DIM];
__device__ float g_r  [N_NODES_C * OUT_DIM];
__device__ int   g_ei_is32;

// ---------------- warp-MMA helpers (sm_80+ PTX, legal on compute_103) --------
__device__ __forceinline__ uint32_t smem_u32(const void* p) {
    uint32_t a;
    asm("{ .reg .u64 t; cvta.to.shared.u64 t, %1; cvt.u32.u64 %0, t; }"
        : "=r"(a) : "l"(p));
    return a;
}
__device__ __forceinline__ void ldsm_x4(uint32_t addr, uint32_t& r0, uint32_t& r1,
                                        uint32_t& r2, uint32_t& r3) {
    asm volatile("ldmatrix.sync.aligned.m8n8.x4.shared.b16 {%0,%1,%2,%3}, [%4];"
                 : "=r"(r0), "=r"(r1), "=r"(r2), "=r"(r3) : "r"(addr) : "memory");
}
__device__ __forceinline__ void mma_bf16(float* c, const uint32_t* a,
                                         uint32_t b0, uint32_t b1) {
    asm volatile("mma.sync.aligned.m16n8k16.row.col.f32.bf16.bf16.f32 "
                 "{%0,%1,%2,%3}, {%4,%5,%6,%7}, {%8,%9}, {%0,%1,%2,%3};"
                 : "+f"(c[0]), "+f"(c[1]), "+f"(c[2]), "+f"(c[3])
                 : "r"(a[0]), "r"(a[1]), "r"(a[2]), "r"(a[3]), "r"(b0), "r"(b1));
}
__device__ __forceinline__ void f2bf_hilo(float v, unsigned short& h, unsigned short& l) {
    __nv_bfloat16 hb = __float2bfloat16_rn(v);
    float r = v - __bfloat162float(hb);
    __nv_bfloat16 lb = __float2bfloat16_rn(r);
    h = __bfloat16_as_ushort(hb);
    l = __bfloat16_as_ushort(lb);
}
__device__ __forceinline__ void f4_to_hilo(float4 v, uint2& hu, uint2& lu) {
    float vv[4] = {v.x, v.y, v.z, v.w};
    unsigned short hs[4], ls[4];
#pragma unroll
    for (int k = 0; k < 4; ++k) f2bf_hilo(vv[k], hs[k], ls[k]);
    hu.x = (uint32_t)hs[0] | ((uint32_t)hs[1] << 16);
    hu.y = (uint32_t)hs[2] | ((uint32_t)hs[3] << 16);
    lu.x = (uint32_t)ls[0] | ((uint32_t)ls[1] << 16);
    lu.y = (uint32_t)ls[2] | ((uint32_t)ls[3] << 16);
}

// smem layout for k_gemm (dynamic): strides in bf16 elements
#define STRA 136                         // 128 data + 8 pad (272B rows)
#define OFF_A  0                         // A/H: 128 rows -> 34816 B
#define OFF_B  34816                     // B (Wcat): 64 rows -> 17408 B
#define OFF_B2 52224                     // B2 (W2cat): 16 rows -> 4352 B
#define OFF_B1 56576                     // b1: 64 floats = 256 B
#define SMEM_GEMM 56832

// ---------------- kernel 1: zero counters + detect edge dtype ---------------
__global__ void k_zero(const void* __restrict__ ei) {
    const int stride = gridDim.x * blockDim.x;
    int t = blockIdx.x * blockDim.x + threadIdx.x;
    if (t == 0) {
        const long long* p = (const long long*)ei;
        int is32 = 0;
        for (int i = 0; i < 128; ++i) {
            long long v = p[i];
            if (v < 0 || v >= (long long)N_NODES_C) { is32 = 1; break; }
        }
        g_ei_is32 = is32;
    }
    for (int i = t; i < N_NODES_C; i += stride) g_cnt[i] = 0;
}

// ---------------- kernel 2: build padded CSR --------------------------------
__global__ void __launch_bounds__(256) k_fill(const void* __restrict__ ei) {
    int e = blockIdx.x * blockDim.x + threadIdx.x;
    if (e >= N_EDGES_C) return;
    int src, dst;
    if (g_ei_is32) {
        const int* p = (const int*)ei;
        src = p[e];
        dst = p[N_EDGES_C + e];
    } else {
        const long long* p = (const long long*)ei;
        src = (int)p[e];
        dst = (int)p[N_EDGES_C + e];
    }
    int slot = atomicAdd(&g_cnt[dst], 1);
    if (slot < MAX_DEG) g_csr[dst * MAX_DEG + slot] = src;
}

// ---------------- kernel 3: gather-mean, 8 lanes per node -------------------
__global__ void __launch_bounds__(256) k_agg(const float* __restrict__ x) {
    __shared__ int sIdx[32 * MAX_DEG];
    __shared__ int sDeg[32];

    int tid = threadIdx.x;
    int base = blockIdx.x * 32;

    for (int i = tid; i < 32 * MAX_DEG; i += 256) {
        int nl = i >> 6;
        sIdx[i] = g_csr[(base + nl) * MAX_DEG + (i & 63)];
    }
    if (tid < 32) sDeg[tid] = min(g_cnt[base + tid], MAX_DEG);
    __syncthreads();

    int qid = tid >> 3, q = tid & 7;
    int deg = sDeg[qid];
    const int* row = &sIdx[qid * MAX_DEG];

    float4 a0 = make_float4(0.f, 0.f, 0.f, 0.f);
    float4 a1 = a0;
    int j = 0;
    for (; j + 2 <= deg; j += 2) {
        int sa = row[j], sb = row[j + 1];
        float4 va = *reinterpret_cast<const float4*>(x + (size_t)sa * IN_DIM + q * 4);
        float4 vb = *reinterpret_cast<const float4*>(x + (size_t)sb * IN_DIM + q * 4);
        a0.x += va.x; a0.y += va.y; a0.z += va.z; a0.w += va.w;
        a1.x += vb.x; a1.y += vb.y; a1.z += vb.z; a1.w += vb.w;
    }
    if (j < deg) {
        float4 va = *reinterpret_cast<const float4*>(x + (size_t)row[j] * IN_DIM + q * 4);
        a0.x += va.x; a0.y += va.y; a0.z += va.z; a0.w += va.w;
    }
    float inv = 1.0f / fmaxf((float)deg, 1.0f);
    float4 o4;
    o4.x = (a0.x + a1.x) * inv;
    o4.y = (a0.y + a1.y) * inv;
    o4.z = (a0.z + a1.z) * inv;
    o4.w = (a0.w + a1.w) * inv;
    *reinterpret_cast<float4*>(g_agg + (size_t)(base + qid) * IN_DIM + q * 4) = o4;
}

// ---------------- kernel 4: double-MMA fused layer (bf16 hi/lo) -------------
__global__ void __launch_bounds__(256, 2) k_gemm(const float* __restrict__ x,
                                                 const float* __restrict__ W1l,
                                                 const float* __restrict__ b1,
                                                 const float* __restrict__ W1r,
                                                 const float* __restrict__ W2l,
                                                 const float* __restrict__ W2r) {
    extern __shared__ unsigned char dynsmem[];
    unsigned short* sA  = reinterpret_cast<unsigned short*>(dynsmem + OFF_A);
    unsigned short* sB  = reinterpret_cast<unsigned short*>(dynsmem + OFF_B);
    unsigned short* sB2 = reinterpret_cast<unsigned short*>(dynsmem + OFF_B2);
    float* sb1 = reinterpret_cast<float*>(dynsmem + OFF_B1);

    const uint32_t sA_u  = smem_u32(sA);
    const uint32_t sB_u  = smem_u32(sB);
    const uint32_t sB2_u = smem_u32(sB2);

    int t = threadIdx.x;
    int wid = t >> 5, lane = t & 31;
    int base = blockIdx.x * NPB;

    // ---- stage A rows: [hi(64) | lo(64)] bf16, feats = (agg | x) ----
    for (int idx = t; idx < NPB * 16; idx += 256) {
        int n = idx >> 4, f4 = idx & 15;
        int node = base + n;
        float4 v = make_float4(0.f, 0.f, 0.f, 0.f);
        if (node < N_NODES_C) {
            v = (f4 < 8)
                ? *reinterpret_cast<const float4*>(g_agg + (size_t)node * IN_DIM + f4 * 4)
                : *reinterpret_cast<const float4*>(x + (size_t)node * IN_DIM + (f4 - 8) * 4);
        }
        uint2 hu, lu;
        f4_to_hilo(v, hu, lu);
        *reinterpret_cast<uint2*>(sA + n * STRA + f4 * 4)      = hu;
        *reinterpret_cast<uint2*>(sA + n * STRA + 64 + f4 * 4) = lu;
    }
    // ---- stage B rows (Wcat [o][f]): [hi(64) | lo(64)] ----
    for (int idx = t; idx < 64 * 16; idx += 256) {
        int o = idx >> 4, f4 = idx & 15;
        float4 v = (f4 < 8)
            ? *reinterpret_cast<const float4*>(W1l + o * IN_DIM + f4 * 4)
            : *reinterpret_cast<const float4*>(W1r + o * IN_DIM + (f4 - 8) * 4);
        uint2 hu, lu;
        f4_to_hilo(v, hu, lu);
        *reinterpret_cast<uint2*>(sB + o * STRA + f4 * 4)      = hu;
        *reinterpret_cast<uint2*>(sB + o * STRA + 64 + f4 * 4) = lu;
    }
    // ---- stage B2 rows (W2cat [16][64]: rows 0-7 = W2l, 8-15 = W2r) ----
    for (int idx = t; idx < 16 * 16; idx += 256) {
        int o2 = idx >> 4, f4 = idx & 15;
        const float* srcw = (o2 < 8) ? (W2l + o2 * HID_DIM) : (W2r + (o2 - 8) * HID_DIM);
        float4 v = *reinterpret_cast<const float4*>(srcw + f4 * 4);
        uint2 hu, lu;
        f4_to_hilo(v, hu, lu);
        *reinterpret_cast<uint2*>(sB2 + o2 * STRA + f4 * 4)      = hu;
        *reinterpret_cast<uint2*>(sB2 + o2 * STRA + 64 + f4 * 4) = lu;
    }
    if (t < HID_DIM) sb1[t] = b1[t];
    __syncthreads();   // the only block-wide sync

    const uint32_t a_base = sA_u + (uint32_t)(((wid * 16 + (lane & 15)) * STRA + (lane >> 4) * 8) * 2);
    const int q = lane >> 3, rr = lane & 7;
    const uint32_t b_base  = sB_u  + (uint32_t)((((q >> 1) * 8 + rr) * STRA + (q & 1) * 8) * 2);
    const uint32_t b2_base = sB2_u + (uint32_t)((((q >> 1) * 8 + rr) * STRA + (q & 1) * 8) * 2);

    const int ka_tab[12] = {0, 1, 2, 3, 4, 5, 6, 7, 0, 1, 2, 3};   // A: hi,lo,hi
    const int kb_tab[12] = {0, 1, 2, 3, 0, 1, 2, 3, 4, 5, 6, 7};   // B: hi,hi,lo

    // ---- MMA1: C[8 ntiles][4] ----
    float c[8][4];
#pragma unroll
    for (int nt = 0; nt < 8; ++nt)
#pragma unroll
        for (int k = 0; k < 4; ++k) c[nt][k] = 0.f;
#pragma unroll
    for (int s = 0; s < 12; ++s) {
        uint32_t a[4];
        ldsm_x4(a_base + (uint32_t)(ka_tab[s] * 32), a[0], a[1], a[2], a[3]);
        uint32_t koff = (uint32_t)(kb_tab[s] * 32);
#pragma unroll
        for (int np = 0; np < 4; ++np) {
            uint32_t b0, b1v, b2v, b3;
            ldsm_x4(b_base + (uint32_t)(np * 16 * STRA * 2) + koff, b0, b1v, b2v, b3);
            mma_bf16(c[2 * np],     a, b0, b1v);
            mma_bf16(c[2 * np + 1], a, b2v, b3);
        }
    }

    // ---- warp-private epilogue: relu(h)+b1 -> own A-slab (bf16 hi/lo) ----
    __syncwarp();
    {
        int g = lane >> 2, cc = lane & 3;
        int m0 = wid * 16 + g;
#pragma unroll
        for (int nt = 0; nt < 8; ++nt) {
            int o0 = nt * 8 + 2 * cc;
            float bi0 = sb1[o0], bi1 = sb1[o0 + 1];
            float v0 = fmaxf(c[nt][0] + bi0, 0.f);
            float v1 = fmaxf(c[nt][1] + bi1, 0.f);
            float v2 = fmaxf(c[nt][2] + bi0, 0.f);
            float v3 = fmaxf(c[nt][3] + bi1, 0.f);
            unsigned short h0, l0, h1, l1, h2, l2, h3, l3;
            f2bf_hilo(v0, h0, l0); f2bf_hilo(v1, h1, l1);
            f2bf_hilo(v2, h2, l2); f2bf_hilo(v3, h3, l3);
            *reinterpret_cast<uint32_t*>(sA + m0 * STRA + o0)            = (uint32_t)h0 | ((uint32_t)h1 << 16);
            *reinterpret_cast<uint32_t*>(sA + m0 * STRA + 64 + o0)       = (uint32_t)l0 | ((uint32_t)l1 << 16);
            *reinterpret_cast<uint32_t*>(sA + (m0 + 8) * STRA + o0)      = (uint32_t)h2 | ((uint32_t)h3 << 16);
            *reinterpret_cast<uint32_t*>(sA + (m0 + 8) * STRA + 64 + o0) = (uint32_t)l2 | ((uint32_t)l3 << 16);
        }
    }
    __syncwarp();

    // ---- MMA2: [p|r][128x16] = H @ W2cat^T ----
    float c2[2][4];
#pragma unroll
    for (int nt = 0; nt < 2; ++nt)
#pragma unroll
        for (int k = 0; k < 4; ++k) c2[nt][k] = 0.f;
#pragma unroll
    for (int s = 0; s < 12; ++s) {
        uint32_t a[4];
        ldsm_x4(a_base + (uint32_t)(ka_tab[s] * 32), a[0], a[1], a[2], a[3]);
        uint32_t b0, b1v, b2v, b3;
        ldsm_x4(b2_base + (uint32_t)(kb_tab[s] * 32), b0, b1v, b2v, b3);
        mma_bf16(c2[0], a, b0, b1v);   // cols 0-7  = p
        mma_bf16(c2[1], a, b2v, b3);   // cols 8-15 = r
    }

    // ---- store p/r from fragments ----
    {
        int g = lane >> 2, cc = lane & 3;
        int m0 = wid * 16 + g;
        int n0 = base + m0, n1 = base + m0 + 8;
        if (n0 < N_NODES_C) {
            *reinterpret_cast<float2*>(g_p + (size_t)n0 * OUT_DIM + 2 * cc) =
                make_float2(c2[0][0], c2[0][1]);
            *reinterpret_cast<float2*>(g_r + (size_t)n0 * OUT_DIM + 2 * cc) =
                make_float2(c2[1][0], c2[1][1]);
        }
        if (n1 < N_NODES_C) {
            *reinterpret_cast<float2*>(g_p + (size_t)n1 * OUT_DIM + 2 * cc) =
                make_float2(c2[0][2], c2[0][3]);
            *reinterpret_cast<float2*>(g_r + (size_t)n1 * OUT_DIM + 2 * cc) =
                make_float2(c2[1][2], c2[1][3]);
        }
    }
}

// ---------------- kernel 5: layer-2 gather (k_agg style, 2 thr/node) --------
// 128 nodes/block; CSR slab staged via coalesced int4 loads; thread = one
// float4 half of the p-row. No shuffles, no per-j predication.
__global__ void __launch_bounds__(256) k_layerB(const float* __restrict__ b2,
                                                float* __restrict__ out) {
    __shared__ int sIdx[128 * MAX_DEG];   // 32KB
    __shared__ int sDeg[128];

    int tid = threadIdx.x;
    int base = blockIdx.x * 128;
    int rows = min(128, N_NODES_C - base);

    // stage CSR slab as int4 (rows*16 int4 loads)
    const int4* gsrc = reinterpret_cast<const int4*>(g_csr + (size_t)base * MAX_DEG);
    int4* sdst = reinterpret_cast<int4*>(sIdx);
    for (int i = tid; i < rows * 16; i += 256) sdst[i] = gsrc[i];
    if (tid < rows) sDeg[tid] = min(g_cnt[base + tid], MAX_DEG);
    __syncthreads();

    int n = tid >> 1, q = tid & 1;
    if (n >= rows) return;
    int node = base + n;
    int deg = sDeg[n];
    const int* row = &sIdx[n * MAX_DEG];

    float4 a0 = make_float4(0.f, 0.f, 0.f, 0.f);
    float4 a1 = a0;
    int j = 0;
    for (; j + 2 <= deg; j += 2) {
        const float4 va = *reinterpret_cast<const float4*>(g_p + (size_t)row[j]     * OUT_DIM + q * 4);
        const float4 vb = *reinterpret_cast<const float4*>(g_p + (size_t)row[j + 1] * OUT_DIM + q * 4);
        a0.x += va.x; a0.y += va.y; a0.z += va.z; a0.w += va.w;
        a1.x += vb.x; a1.y += vb.y; a1.z += vb.z; a1.w += vb.w;
    }
    if (j < deg) {
        const float4 va = *reinterpret_cast<const float4*>(g_p + (size_t)row[j] * OUT_DIM + q * 4);
        a0.x += va.x; a0.y += va.y; a0.z += va.z; a0.w += va.w;
    }
    float inv = 1.0f / fmaxf((float)deg, 1.0f);
    float4 b4 = *reinterpret_cast<const float4*>(b2 + q * 4);
    float4 r  = *reinterpret_cast<const float4*>(g_r + (size_t)node * OUT_DIM + q * 4);
    float4 o4;
    o4.x = fmaf(a0.x + a1.x, inv, b4.x) + r.x;
    o4.y = fmaf(a0.y + a1.y, inv, b4.y) + r.y;
    o4.z = fmaf(a0.z + a1.z, inv, b4.z) + r.z;
    o4.w = fmaf(a0.w + a1.w, inv, b4.w) + r.w;
    *reinterpret_cast<float4*>(out + (size_t)node * OUT_DIM + q * 4) = o4;
}

// ---------------- launcher ---------------------------------------------------
extern "C" void kernel_launch(void* const* d_in, const int* in_sizes, int n_in,
                              void* d_out, int out_size) {
    int ix, iei, iW1l, ib1, iW1r, iW2l, ib2, iW2r;
    if (in_sizes[0] > 1000000) {        // dict order (x first)
        ix = 0; iei = 1; iW1l = 2; ib1 = 3; iW1r = 4; iW2l = 5; ib2 = 6; iW2r = 7;
    } else {                            // alphabetical
        iW1l = 0; iW1r = 1; iW2l = 2; iW2r = 3; ib1 = 4; ib2 = 5; iei = 6; ix = 7;
    }
    const float* x   = (const float*)d_in[ix];
    const void*  ei  = d_in[iei];
    const float* W1l = (const float*)d_in[iW1l];
    const float* b1  = (const float*)d_in[ib1];
    const float* W1r = (const float*)d_in[iW1r];
    const float* W2l = (const float*)d_in[iW2l];
    const float* b2  = (const float*)d_in[ib2];
    const float* W2r = (const float*)d_in[iW2r];
    float* out = (float*)d_out;

    static int smem_set = 0;
    if (!smem_set) {
        cudaFuncSetAttribute(k_gemm, cudaFuncAttributeMaxDynamicSharedMemorySize, SMEM_GEMM);
        cudaFuncSetAttribute(k_gemm, cudaFuncAttributePreferredSharedMemoryCarveout, 100);
        smem_set = 1;
    }

    k_zero<<<512, 256>>>(ei);
    k_fill<<<(N_EDGES_C + 255) / 256, 256>>>(ei);
    k_agg<<<N_NODES_C / 32, 256>>>(x);
    k_gemm<<<(N_NODES_C + NPB - 1) / NPB, 256, SMEM_GEMM>>>(x, W1l, b1, W1r, W2l, W2r);
    k_layerB<<<(N_NODES_C + 127) / 128, 256>>>(b2, out);
}

// round 11
// speedup vs baseline: 1.1611x; 1.0220x over previous
#include <cuda_runtime.h>
#include <cuda_bf16.h>
#include <stdint.h>

#define N_NODES_C 100000
#define N_EDGES_C 1600000
#define IN_DIM 32
#define HID_DIM 64
#define OUT_DIM 8
#define MAX_DEG 64
#define NPB 64               // nodes per k_gemm block (MMA M)

typedef unsigned long long ull;

// ---------------- scratch (device globals; no allocation allowed) ----------
__device__ int   g_cnt[N_NODES_C];
__device__ int   g_csr[N_NODES_C * MAX_DEG];
__device__ float g_agg[N_NODES_C * IN_DIM];
__device__ float g_p  [N_NODES_C * OUT_DIM];
__device__ float g_r  [N_NODES_C * OUT_DIM];
__device__ int   g_ei_is32;

// ---------------- warp-MMA helpers (sm_80+ PTX, legal on compute_103) --------
__device__ __forceinline__ uint32_t smem_u32(const void* p) {
    uint32_t a;
    asm("{ .reg .u64 t; cvta.to.shared.u64 t, %1; cvt.u32.u64 %0, t; }"
        : "=r"(a) : "l"(p));
    return a;
}
__device__ __forceinline__ void ldsm_x4(uint32_t addr, uint32_t& r0, uint32_t& r1,
                                        uint32_t& r2, uint32_t& r3) {
    asm volatile("ldmatrix.sync.aligned.m8n8.x4.shared.b16 {%0,%1,%2,%3}, [%4];"
                 : "=r"(r0), "=r"(r1), "=r"(r2), "=r"(r3) : "r"(addr) : "memory");
}
__device__ __forceinline__ void mma_bf16(float* c, const uint32_t* a,
                                         uint32_t b0, uint32_t b1) {
    asm volatile("mma.sync.aligned.m16n8k16.row.col.f32.bf16.bf16.f32 "
                 "{%0,%1,%2,%3}, {%4,%5,%6,%7}, {%8,%9}, {%0,%1,%2,%3};"
                 : "+f"(c[0]), "+f"(c[1]), "+f"(c[2]), "+f"(c[3])
                 : "r"(a[0]), "r"(a[1]), "r"(a[2]), "r"(a[3]), "r"(b0), "r"(b1));
}
__device__ __forceinline__ void f2bf_hilo(float v, unsigned short& h, unsigned short& l) {
    __nv_bfloat16 hb = __float2bfloat16_rn(v);
    float r = v - __bfloat162float(hb);
    __nv_bfloat16 lb = __float2bfloat16_rn(r);
    h = __bfloat16_as_ushort(hb);
    l = __bfloat16_as_ushort(lb);
}
__device__ __forceinline__ void f4_to_hilo(float4 v, uint2& hu, uint2& lu) {
    float vv[4] = {v.x, v.y, v.z, v.w};
    unsigned short hs[4], ls[4];
#pragma unroll
    for (int k = 0; k < 4; ++k) f2bf_hilo(vv[k], hs[k], ls[k]);
    hu.x = (uint32_t)hs[0] | ((uint32_t)hs[1] << 16);
    hu.y = (uint32_t)hs[2] | ((uint32_t)hs[3] << 16);
    lu.x = (uint32_t)ls[0] | ((uint32_t)ls[1] << 16);
    lu.y = (uint32_t)ls[2] | ((uint32_t)ls[3] << 16);
}

// smem layout for k_gemm (dynamic): strides in bf16 elements
#define STRA 136                         // 128 data + 8 pad (272B rows)
#define OFF_A  0                         // A/H: 64 rows -> 17408 B
#define OFF_B  17408                     // B (Wcat): 64 rows -> 17408 B
#define OFF_B2 34816                     // B2 (W2cat): 16 rows -> 4352 B
#define OFF_B1 39168                     // b1: 64 floats = 256 B
#define SMEM_GEMM 39424

// ---------------- kernel 1: zero counters + detect edge dtype ---------------
__global__ void k_zero(const void* __restrict__ ei) {
    const int stride = gridDim.x * blockDim.x;
    int t = blockIdx.x * blockDim.x + threadIdx.x;
    if (t == 0) {
        const long long* p = (const long long*)ei;
        int is32 = 0;
        for (int i = 0; i < 128; ++i) {
            long long v = p[i];
            if (v < 0 || v >= (long long)N_NODES_C) { is32 = 1; break; }
        }
        g_ei_is32 = is32;
    }
    for (int i = t; i < N_NODES_C; i += stride) g_cnt[i] = 0;
}

// ---------------- kernel 2: build padded CSR --------------------------------
__global__ void __launch_bounds__(256) k_fill(const void* __restrict__ ei) {
    int e = blockIdx.x * blockDim.x + threadIdx.x;
    if (e >= N_EDGES_C) return;
    int src, dst;
    if (g_ei_is32) {
        const int* p = (const int*)ei;
        src = p[e];
        dst = p[N_EDGES_C + e];
    } else {
        const long long* p = (const long long*)ei;
        src = (int)p[e];
        dst = (int)p[N_EDGES_C + e];
    }
    int slot = atomicAdd(&g_cnt[dst], 1);
    if (slot < MAX_DEG) g_csr[dst * MAX_DEG + slot] = src;
}

// ---------------- kernel 3: gather-mean, 8 lanes per node -------------------
__global__ void __launch_bounds__(256) k_agg(const float* __restrict__ x) {
    __shared__ int sIdx[32 * MAX_DEG];
    __shared__ int sDeg[32];

    int tid = threadIdx.x;
    int base = blockIdx.x * 32;

    for (int i = tid; i < 32 * MAX_DEG; i += 256) {
        int nl = i >> 6;
        sIdx[i] = g_csr[(base + nl) * MAX_DEG + (i & 63)];
    }
    if (tid < 32) sDeg[tid] = min(g_cnt[base + tid], MAX_DEG);
    __syncthreads();

    int qid = tid >> 3, q = tid & 7;
    int deg = sDeg[qid];
    const int* row = &sIdx[qid * MAX_DEG];

    float4 a0 = make_float4(0.f, 0.f, 0.f, 0.f);
    float4 a1 = a0;
    int j = 0;
    for (; j + 2 <= deg; j += 2) {
        int sa = row[j], sb = row[j + 1];
        float4 va = *reinterpret_cast<const float4*>(x + (size_t)sa * IN_DIM + q * 4);
        float4 vb = *reinterpret_cast<const float4*>(x + (size_t)sb * IN_DIM + q * 4);
        a0.x += va.x; a0.y += va.y; a0.z += va.z; a0.w += va.w;
        a1.x += vb.x; a1.y += vb.y; a1.z += vb.z; a1.w += vb.w;
    }
    if (j < deg) {
        float4 va = *reinterpret_cast<const float4*>(x + (size_t)row[j] * IN_DIM + q * 4);
        a0.x += va.x; a0.y += va.y; a0.z += va.z; a0.w += va.w;
    }
    float inv = 1.0f / fmaxf((float)deg, 1.0f);
    float4 o4;
    o4.x = (a0.x + a1.x) * inv;
    o4.y = (a0.y + a1.y) * inv;
    o4.z = (a0.z + a1.z) * inv;
    o4.w = (a0.w + a1.w) * inv;
    *reinterpret_cast<float4*>(g_agg + (size_t)(base + qid) * IN_DIM + q * 4) = o4;
}

// ---------------- kernel 4: double-MMA fused layer, M=64 tile ---------------
// warp = (row-group wid>>1: 16 rows, col-half wid&1: 32 cols).
// MMA1: D[64x64]; epilogue h -> A-slab; MMA2 (col-half-0 warps): [p|r][64x16].
__global__ void __launch_bounds__(256, 3) k_gemm(const float* __restrict__ x,
                                                 const float* __restrict__ W1l,
                                                 const float* __restrict__ b1,
                                                 const float* __restrict__ W1r,
                                                 const float* __restrict__ W2l,
                                                 const float* __restrict__ W2r) {
    extern __shared__ unsigned char dynsmem[];
    unsigned short* sA  = reinterpret_cast<unsigned short*>(dynsmem + OFF_A);
    unsigned short* sB  = reinterpret_cast<unsigned short*>(dynsmem + OFF_B);
    unsigned short* sB2 = reinterpret_cast<unsigned short*>(dynsmem + OFF_B2);
    float* sb1 = reinterpret_cast<float*>(dynsmem + OFF_B1);

    const uint32_t sA_u  = smem_u32(sA);
    const uint32_t sB_u  = smem_u32(sB);
    const uint32_t sB2_u = smem_u32(sB2);

    int t = threadIdx.x;
    int wid = t >> 5, lane = t & 31;
    int rg = wid >> 1, ch = wid & 1;
    int base = blockIdx.x * NPB;

    // ---- stage A rows (64): [hi(64) | lo(64)] bf16, feats = (agg | x) ----
    for (int idx = t; idx < NPB * 16; idx += 256) {
        int n = idx >> 4, f4 = idx & 15;
        int node = base + n;
        float4 v = make_float4(0.f, 0.f, 0.f, 0.f);
        if (node < N_NODES_C) {
            v = (f4 < 8)
                ? *reinterpret_cast<const float4*>(g_agg + (size_t)node * IN_DIM + f4 * 4)
                : *reinterpret_cast<const float4*>(x + (size_t)node * IN_DIM + (f4 - 8) * 4);
        }
        uint2 hu, lu;
        f4_to_hilo(v, hu, lu);
        *reinterpret_cast<uint2*>(sA + n * STRA + f4 * 4)      = hu;
        *reinterpret_cast<uint2*>(sA + n * STRA + 64 + f4 * 4) = lu;
    }
    // ---- stage B rows (Wcat [o][f]): [hi(64) | lo(64)] ----
    for (int idx = t; idx < 64 * 16; idx += 256) {
        int o = idx >> 4, f4 = idx & 15;
        float4 v = (f4 < 8)
            ? *reinterpret_cast<const float4*>(W1l + o * IN_DIM + f4 * 4)
            : *reinterpret_cast<const float4*>(W1r + o * IN_DIM + (f4 - 8) * 4);
        uint2 hu, lu;
        f4_to_hilo(v, hu, lu);
        *reinterpret_cast<uint2*>(sB + o * STRA + f4 * 4)      = hu;
        *reinterpret_cast<uint2*>(sB + o * STRA + 64 + f4 * 4) = lu;
    }
    // ---- stage B2 rows (W2cat [16][64]: rows 0-7 = W2l, 8-15 = W2r) ----
    for (int idx = t; idx < 16 * 16; idx += 256) {
        int o2 = idx >> 4, f4 = idx & 15;
        const float* srcw = (o2 < 8) ? (W2l + o2 * HID_DIM) : (W2r + (o2 - 8) * HID_DIM);
        float4 v = *reinterpret_cast<const float4*>(srcw + f4 * 4);
        uint2 hu, lu;
        f4_to_hilo(v, hu, lu);
        *reinterpret_cast<uint2*>(sB2 + o2 * STRA + f4 * 4)      = hu;
        *reinterpret_cast<uint2*>(sB2 + o2 * STRA + 64 + f4 * 4) = lu;
    }
    if (t < HID_DIM) sb1[t] = b1[t];
    __syncthreads();

    // fragment base addresses
    const uint32_t a_base = sA_u + (uint32_t)(((rg * 16 + (lane & 15)) * STRA + (lane >> 4) * 8) * 2);
    const int q = lane >> 3, rr = lane & 7;
    const uint32_t b_base  = sB_u  + (uint32_t)(((ch * 32 + (q >> 1) * 8 + rr) * STRA + (q & 1) * 8) * 2);
    const uint32_t b2_base = sB2_u + (uint32_t)((((q >> 1) * 8 + rr) * STRA + (q & 1) * 8) * 2);

    const int ka_tab[12] = {0, 1, 2, 3, 4, 5, 6, 7, 0, 1, 2, 3};   // A: hi,lo,hi
    const int kb_tab[12] = {0, 1, 2, 3, 0, 1, 2, 3, 4, 5, 6, 7};   // B: hi,hi,lo

    // ---- MMA1: warp covers 16 rows x 32 cols -> c[4 ntiles][4] ----
    float c[4][4];
#pragma unroll
    for (int nt = 0; nt < 4; ++nt)
#pragma unroll
        for (int k = 0; k < 4; ++k) c[nt][k] = 0.f;
#pragma unroll
    for (int s = 0; s < 12; ++s) {
        uint32_t a[4];
        ldsm_x4(a_base + (uint32_t)(ka_tab[s] * 32), a[0], a[1], a[2], a[3]);
        uint32_t koff = (uint32_t)(kb_tab[s] * 32);
#pragma unroll
        for (int np = 0; np < 2; ++np) {
            uint32_t b0, b1v, b2v, b3;
            ldsm_x4(b_base + (uint32_t)(np * 16 * STRA * 2) + koff, b0, b1v, b2v, b3);
            mma_bf16(c[2 * np],     a, b0, b1v);
            mma_bf16(c[2 * np + 1], a, b2v, b3);
        }
    }

    // ---- epilogue: relu(h)+b1 -> A-slab (bf16 hi/lo); rows shared by 2 warps
    {
        int g = lane >> 2, cc = lane & 3;
        int m0 = rg * 16 + g;
#pragma unroll
        for (int nt = 0; nt < 4; ++nt) {
            int o0 = ch * 32 + nt * 8 + 2 * cc;
            float bi0 = sb1[o0], bi1 = sb1[o0 + 1];
            float v0 = fmaxf(c[nt][0] + bi0, 0.f);
            float v1 = fmaxf(c[nt][1] + bi1, 0.f);
            float v2 = fmaxf(c[nt][2] + bi0, 0.f);
            float v3 = fmaxf(c[nt][3] + bi1, 0.f);
            unsigned short h0, l0, h1, l1, h2, l2, h3, l3;
            f2bf_hilo(v0, h0, l0); f2bf_hilo(v1, h1, l1);
            f2bf_hilo(v2, h2, l2); f2bf_hilo(v3, h3, l3);
            *reinterpret_cast<uint32_t*>(sA + m0 * STRA + o0)            = (uint32_t)h0 | ((uint32_t)h1 << 16);
            *reinterpret_cast<uint32_t*>(sA + m0 * STRA + 64 + o0)       = (uint32_t)l0 | ((uint32_t)l1 << 16);
            *reinterpret_cast<uint32_t*>(sA + (m0 + 8) * STRA + o0)      = (uint32_t)h2 | ((uint32_t)h3 << 16);
            *reinterpret_cast<uint32_t*>(sA + (m0 + 8) * STRA + 64 + o0) = (uint32_t)l2 | ((uint32_t)l3 << 16);
        }
    }
    __syncthreads();   // h rows complete (both col-halves) before MMA2 reads

    // ---- MMA2 (col-half-0 warps only): [p|r][64x16] = H @ W2cat^T ----
    if (ch == 0) {
        float c2[2][4];
#pragma unroll
        for (int nt = 0; nt < 2; ++nt)
#pragma unroll
            for (int k = 0; k < 4; ++k) c2[nt][k] = 0.f;
#pragma unroll
        for (int s = 0; s < 12; ++s) {
            uint32_t a[4];
            ldsm_x4(a_base + (uint32_t)(ka_tab[s] * 32), a[0], a[1], a[2], a[3]);
            uint32_t b0, b1v, b2v, b3;
            ldsm_x4(b2_base + (uint32_t)(kb_tab[s] * 32), b0, b1v, b2v, b3);
            mma_bf16(c2[0], a, b0, b1v);   // cols 0-7  = p
            mma_bf16(c2[1], a, b2v, b3);   // cols 8-15 = r
        }
        int g = lane >> 2, cc = lane & 3;
        int m0 = rg * 16 + g;
        int n0 = base + m0, n1 = base + m0 + 8;
        if (n0 < N_NODES_C) {
            *reinterpret_cast<float2*>(g_p + (size_t)n0 * OUT_DIM + 2 * cc) =
                make_float2(c2[0][0], c2[0][1]);
            *reinterpret_cast<float2*>(g_r + (size_t)n0 * OUT_DIM + 2 * cc) =
                make_float2(c2[1][0], c2[1][1]);
        }
        if (n1 < N_NODES_C) {
            *reinterpret_cast<float2*>(g_p + (size_t)n1 * OUT_DIM + 2 * cc) =
                make_float2(c2[0][2], c2[0][3]);
            *reinterpret_cast<float2*>(g_r + (size_t)n1 * OUT_DIM + 2 * cc) =
                make_float2(c2[1][2], c2[1][3]);
        }
    }
}

// ---------------- kernel 5: layer-2 gather (2 thr/node, staged CSR) ---------
__global__ void __launch_bounds__(256) k_layerB(const float* __restrict__ b2,
                                                float* __restrict__ out) {
    __shared__ int sIdx[128 * MAX_DEG];   // 32KB
    __shared__ int sDeg[128];

    int tid = threadIdx.x;
    int base = blockIdx.x * 128;
    int rows = min(128, N_NODES_C - base);

    const int4* gsrc = reinterpret_cast<const int4*>(g_csr + (size_t)base * MAX_DEG);
    int4* sdst = reinterpret_cast<int4*>(sIdx);
    for (int i = tid; i < rows * 16; i += 256) sdst[i] = gsrc[i];
    if (tid < rows) sDeg[tid] = min(g_cnt[base + tid], MAX_DEG);
    __syncthreads();

    int n = tid >> 1, q = tid & 1;
    if (n >= rows) return;
    int node = base + n;
    int deg = sDeg[n];
    const int* row = &sIdx[n * MAX_DEG];

    float4 a0 = make_float4(0.f, 0.f, 0.f, 0.f);
    float4 a1 = a0;
    int j = 0;
    for (; j + 2 <= deg; j += 2) {
        const float4 va = *reinterpret_cast<const float4*>(g_p + (size_t)row[j]     * OUT_DIM + q * 4);
        const float4 vb = *reinterpret_cast<const float4*>(g_p + (size_t)row[j + 1] * OUT_DIM + q * 4);
        a0.x += va.x; a0.y += va.y; a0.z += va.z; a0.w += va.w;
        a1.x += vb.x; a1.y += vb.y; a1.z += vb.z; a1.w += vb.w;
    }
    if (j < deg) {
        const float4 va = *reinterpret_cast<const float4*>(g_p + (size_t)row[j] * OUT_DIM + q * 4);
        a0.x += va.x; a0.y += va.y; a0.z += va.z; a0.w += va.w;
    }
    float inv = 1.0f / fmaxf((float)deg, 1.0f);
    float4 b4 = *reinterpret_cast<const float4*>(b2 + q * 4);
    float4 r  = *reinterpret_cast<const float4*>(g_r + (size_t)node * OUT_DIM + q * 4);
    float4 o4;
    o4.x = fmaf(a0.x + a1.x, inv, b4.x) + r.x;
    o4.y = fmaf(a0.y + a1.y, inv, b4.y) + r.y;
    o4.z = fmaf(a0.z + a1.z, inv, b4.z) + r.z;
    o4.w = fmaf(a0.w + a1.w, inv, b4.w) + r.w;
    *reinterpret_cast<float4*>(out + (size_t)node * OUT_DIM + q * 4) = o4;
}

// ---------------- launcher ---------------------------------------------------
extern "C" void kernel_launch(void* const* d_in, const int* in_sizes, int n_in,
                              void* d_out, int out_size) {
    int ix, iei, iW1l, ib1, iW1r, iW2l, ib2, iW2r;
    if (in_sizes[0] > 1000000) {        // dict order (x first)
        ix = 0; iei = 1; iW1l = 2; ib1 = 3; iW1r = 4; iW2l = 5; ib2 = 6; iW2r = 7;
    } else {                            // alphabetical
        iW1l = 0; iW1r = 1; iW2l = 2; iW2r = 3; ib1 = 4; ib2 = 5; iei = 6; ix = 7;
    }
    const float* x   = (const float*)d_in[ix];
    const void*  ei  = d_in[iei];
    const float* W1l = (const float*)d_in[iW1l];
    const float* b1  = (const float*)d_in[ib1];
    const float* W1r = (const float*)d_in[iW1r];
    const float* W2l = (const float*)d_in[iW2l];
    const float* b2  = (const float*)d_in[ib2];
    const float* W2r = (const float*)d_in[iW2r];
    float* out = (float*)d_out;

    static int smem_set = 0;
    if (!smem_set) {
        cudaFuncSetAttribute(k_gemm, cudaFuncAttributeMaxDynamicSharedMemorySize, SMEM_GEMM);
        cudaFuncSetAttribute(k_gemm, cudaFuncAttributePreferredSharedMemoryCarveout, 100);
        smem_set = 1;
    }

    k_zero<<<512, 256>>>(ei);
    k_fill<<<(N_EDGES_C + 255) / 256, 256>>>(ei);
    k_agg<<<N_NODES_C / 32, 256>>>(x);
    k_gemm<<<(N_NODES_C + NPB - 1) / NPB, 256, SMEM_GEMM>>>(x, W1l, b1, W1r, W2l, W2r);
    k_layerB<<<(N_NODES_C + 127) / 128, 256>>>(b2, out);
}